// round 4
// baseline (speedup 1.0000x reference)
#include <cuda_runtime.h>

// Sinkhorn, restructured:
//   E = exp(-C/eps) precomputed once (+ transposed copy for coalesced col pass)
//   a = p ./ (E b + P*b_pad);  b = p ./ (E^T a + P*a_pad)   (pure GEMV loop)
//   out = 4096 * min(1, a_i * b_j * E_ij)  (block structure for the padding)
//
// Persistent-kernel iteration: 128 CTAs (strictly fewer than SM count on both
// B300/148 and GB300/152, occupancy 1 -> co-residency guaranteed), software
// grid barrier on per-CTA flag slots with release/acquire threadfences.

#define SK_N     2048
#define SK_NT    4096
#define SK_STEPS 50
#define SK_NBLK  128
#define SK_NTHR  512

__device__ float g_E [SK_N * SK_N];
__device__ float g_ET[SK_N * SK_N];
__device__ float g_a[SK_N];
__device__ float g_b[SK_N];
__device__ float g_apad;
__device__ float g_bpad;
__device__ volatile unsigned g_arrive[SK_NBLK];

// ---------------------------------------------------------------------------
// Kernel 1: E = exp(-C/eps), ET = transpose(E), init state + barrier flags
// ---------------------------------------------------------------------------
__global__ void k_prep(const float* __restrict__ C) {
    __shared__ float tile[32][33];
    const int bx = blockIdx.x, by = blockIdx.y;
    const int tx = threadIdx.x, ty = threadIdx.y;   // (32, 8)
    const float inv_eps = 20.0f;                    // 1/0.05

#pragma unroll
    for (int k = 0; k < 4; k++) {
        int r = by * 32 + ty + 8 * k;
        int c = bx * 32 + tx;
        float e = expf(-C[(size_t)r * SK_N + c] * inv_eps);
        g_E[(size_t)r * SK_N + c] = e;
        tile[ty + 8 * k][tx] = e;
    }
    __syncthreads();
#pragma unroll
    for (int k = 0; k < 4; k++) {
        int r = bx * 32 + ty + 8 * k;   // transposed row
        int c = by * 32 + tx;
        g_ET[(size_t)r * SK_N + c] = tile[tx][ty + 8 * k];
    }

    if (bx == 0 && by == 0) {
        int tid = ty * 32 + tx;          // 0..255
        for (int i = tid; i < SK_N; i += 256) g_b[i] = 1.0f;   // v0 = 0 -> b = 1
        if (tid < SK_NBLK) g_arrive[tid] = 0u;
    }
}

// ---------------------------------------------------------------------------
// Kernel 2: persistent iteration kernel (128 CTAs, software grid barrier)
// ---------------------------------------------------------------------------
__device__ __forceinline__ float wred(float x) {
#pragma unroll
    for (int o = 16; o > 0; o >>= 1) x += __shfl_xor_sync(0xffffffffu, x, o);
    return x;
}

__global__ void __launch_bounds__(SK_NTHR, 1) k_iter() {
    __shared__ float vec[SK_N];     // 8KB staging of b (row pass) / a (col pass)
    __shared__ float wsum[16];

    const int tid  = threadIdx.x;
    const int bid  = blockIdx.x;
    const int wid  = tid >> 5;
    const int lane = tid & 31;
    const int row  = bid * 16 + wid;            // exactly one matrix row per warp
    const float P     = 2048.0f;                // padded rows/cols count
    const float PMARG = 1.0f / 4096.0f;         // p = q = 1/n

    unsigned gen = 0;
    float b_pad = 1.0f;

    for (int it = 0; it < SK_STEPS; ++it) {
        // ================= row pass: a = p / (E b + P b_pad) =================
        float4 v4 = __ldcg(((const float4*)g_b) + tid);
        ((float4*)vec)[tid] = v4;
        float part = wred(v4.x + v4.y + v4.z + v4.w);
        if (lane == 0) wsum[wid] = part;
        __syncthreads();
        float sum_b = 0.0f;
#pragma unroll
        for (int k = 0; k < 16; k++) sum_b += wsum[k];     // deterministic order
        const float a_pad = PMARG / (sum_b + P * b_pad);

        {
            const float4* Er = (const float4*)(g_E + (size_t)row * SK_N);
            const float4* B  = (const float4*)vec;
            float acc = 0.0f;
#pragma unroll
            for (int k = 0; k < 16; k++) {
                float4 e = Er[lane + 32 * k];
                float4 b = B [lane + 32 * k];
                acc = fmaf(e.x, b.x, acc); acc = fmaf(e.y, b.y, acc);
                acc = fmaf(e.z, b.z, acc); acc = fmaf(e.w, b.w, acc);
            }
            acc = wred(acc);
            if (lane == 0) g_a[row] = PMARG / (acc + P * b_pad);
        }

        // ---- grid barrier (release store, spin, acquire fence) ----
        ++gen;
        __threadfence();
        __syncthreads();
        if (tid == 0) g_arrive[bid] = gen;
        if (tid < SK_NBLK) { while (g_arrive[tid] < gen) { } }
        __threadfence();
        __syncthreads();

        // ================= col pass: b = p / (E^T a + P a_pad) ===============
        float4 a4 = __ldcg(((const float4*)g_a) + tid);
        ((float4*)vec)[tid] = a4;
        float parta = wred(a4.x + a4.y + a4.z + a4.w);
        if (lane == 0) wsum[wid] = parta;
        __syncthreads();
        float sum_a = 0.0f;
#pragma unroll
        for (int k = 0; k < 16; k++) sum_a += wsum[k];
        b_pad = PMARG / (sum_a + P * a_pad);

        {
            const float4* Er = (const float4*)(g_ET + (size_t)row * SK_N);
            const float4* A  = (const float4*)vec;
            float acc = 0.0f;
#pragma unroll
            for (int k = 0; k < 16; k++) {
                float4 e = Er[lane + 32 * k];
                float4 a = A [lane + 32 * k];
                acc = fmaf(e.x, a.x, acc); acc = fmaf(e.y, a.y, acc);
                acc = fmaf(e.z, a.z, acc); acc = fmaf(e.w, a.w, acc);
            }
            acc = wred(acc);
            if (lane == 0) g_b[row] = PMARG / (acc + P * a_pad);
        }

        if (it == SK_STEPS - 1 && bid == 0 && tid == 0) {
            g_apad = a_pad;
            g_bpad = b_pad;
        }

        // ---- grid barrier ----
        ++gen;
        __threadfence();
        __syncthreads();
        if (tid == 0) g_arrive[bid] = gen;
        if (tid < SK_NBLK) { while (g_arrive[tid] < gen) { } }
        __threadfence();
        __syncthreads();
    }
}

// ---------------------------------------------------------------------------
// Kernel 3: out[i][j] = 4096 * min(1, a_i * b_j * E_ij), with padded blocks
// ---------------------------------------------------------------------------
__global__ void k_out(float* __restrict__ out) {
    const int i = blockIdx.x;                 // 0..4095 (one output row)
    const float S  = 4096.0f;
    const float ap = g_apad;
    const float bp = g_bpad;
    float4* orow = (float4*)(out + (size_t)i * SK_NT);
    const float4* B4 = (const float4*)g_b;

    if (i < SK_N) {
        const float ai = g_a[i];
        const float4* Er = (const float4*)(g_E + (size_t)i * SK_N);
        for (int t = threadIdx.x; t < 512; t += blockDim.x) {
            float4 e = Er[t], b = B4[t], r;
            r.x = S * fminf(1.0f, ai * b.x * e.x);
            r.y = S * fminf(1.0f, ai * b.y * e.y);
            r.z = S * fminf(1.0f, ai * b.z * e.z);
            r.w = S * fminf(1.0f, ai * b.w * e.w);
            orow[t] = r;
        }
        float c = S * fminf(1.0f, ai * bp);
        float4 c4 = make_float4(c, c, c, c);
        for (int t = threadIdx.x; t < 512; t += blockDim.x) orow[512 + t] = c4;
    } else {
        for (int t = threadIdx.x; t < 512; t += blockDim.x) {
            float4 b = B4[t], r;
            r.x = S * fminf(1.0f, ap * b.x);
            r.y = S * fminf(1.0f, ap * b.y);
            r.z = S * fminf(1.0f, ap * b.z);
            r.w = S * fminf(1.0f, ap * b.w);
            orow[t] = r;
        }
        float c = S * fminf(1.0f, ap * bp);
        float4 c4 = make_float4(c, c, c, c);
        for (int t = threadIdx.x; t < 512; t += blockDim.x) orow[512 + t] = c4;
    }
}

// ---------------------------------------------------------------------------
extern "C" void kernel_launch(void* const* d_in, const int* in_sizes, int n_in,
                              void* d_out, int out_size) {
    const float* C = (const float*)d_in[0];
    float* out = (float*)d_out;

    dim3 tg(32, 8);
    dim3 bg(SK_N / 32, SK_N / 32);
    k_prep<<<bg, tg>>>(C);
    k_iter<<<SK_NBLK, SK_NTHR>>>();
    k_out<<<SK_NT, 256>>>(out);
}